// round 17
// baseline (speedup 1.0000x reference)
#include <cuda_runtime.h>
#include <cuda_fp16.h>
#include <cstdint>
#include <cstddef>

// ---------------- problem constants ----------------
#define T_TOK 4096
#define D_DIM 1024
#define F_DIM 2816
#define F2_DIM 5632
#define N_EXP 8
#define TK 8192

// ---------------- tiling ----------------
// BM=128, BN=64, BK=32, 256 threads, warps 2m x 2n x 2k, 2 CTAs/SM.
// gemm2 (fp16 Wd): 6 stages x 12KB (R15 path).
// gemm1 (f32 Wgu, converted in smem once per stage): 5 stages x 20KB.
#define A_ST 8192                      // A fp16: 128 rows * 64 B
#define B16_ST 4096                    // B fp16: 64 rows * 64 B
#define STG2 (A_ST + B16_ST)           // 12 KB
#define NST2 6
#define SMEM2 (NST2 * STG2)            // 72 KB

#define BF32_OFF 8192                  // f32 B staging: 64 rows * 128 B
#define BF16_OFF 16384                 // fp16 B final: 64 rows * 64 B
#define STG1 20480                     // 20 KB
#define NST1 5
#define SMEM1 (NST1 * STG1)            // 100 KB

#define GRIDX 9
#define G1Y (F_DIM / 32)               // 88
#define WDCVT_Y 4                      // Wd-conversion rider blocks in gemm1
#define NXB 256                        // prep conversion blocks (X only)

// ---------------- device scratch ----------------
__device__ int    g_offsets[N_EXP + 1];
__device__ int    g_tok[TK];
__device__ int    g_pos[TK];
__device__ float  g_wt[TK];
__device__ __half g_xh[(size_t)T_TOK * D_DIM];
__device__ __half g_wdh[(size_t)N_EXP * D_DIM * F_DIM];
__device__ __half g_h[(size_t)TK * F_DIM];
__device__ float  g_o[(size_t)TK * D_DIM];

// ---------------- helpers ----------------
__device__ __forceinline__ uint32_t cvta_s(const void* p) {
    return (uint32_t)__cvta_generic_to_shared(p);
}
__device__ __forceinline__ void cpasync16(uint32_t smem_addr, const void* gptr) {
    asm volatile("cp.async.cg.shared.global [%0], [%1], 16;" ::"r"(smem_addr), "l"(gptr));
}
__device__ __forceinline__ void cp_commit() { asm volatile("cp.async.commit_group;"); }
__device__ __forceinline__ void cp_waitg(int left) {
    if (left <= 0) asm volatile("cp.async.wait_group 0;");
    else if (left == 1) asm volatile("cp.async.wait_group 1;");
    else if (left == 2) asm volatile("cp.async.wait_group 2;");
    else if (left == 3) asm volatile("cp.async.wait_group 3;");
    else asm volatile("cp.async.wait_group 4;");
}
__device__ __forceinline__ void ldsm4(uint32_t r[4], uint32_t addr) {
    asm volatile("ldmatrix.sync.aligned.m8n8.x4.shared.b16 {%0,%1,%2,%3}, [%4];"
                 : "=r"(r[0]), "=r"(r[1]), "=r"(r[2]), "=r"(r[3]) : "r"(addr));
}
__device__ __forceinline__ void mma_f16(float c[4], const uint32_t a[4],
                                        uint32_t b0, uint32_t b1) {
    asm volatile(
        "mma.sync.aligned.m16n8k16.row.col.f32.f16.f16.f32 "
        "{%0,%1,%2,%3},{%4,%5,%6,%7},{%8,%9},{%0,%1,%2,%3};"
        : "+f"(c[0]), "+f"(c[1]), "+f"(c[2]), "+f"(c[3])
        : "r"(a[0]), "r"(a[1]), "r"(a[2]), "r"(a[3]), "r"(b0), "r"(b1));
}
__device__ __forceinline__ uint32_t pack_h2(float x, float y) {
    __half2 h = __float22half2_rn(make_float2(x, y));
    return *reinterpret_cast<uint32_t*>(&h);
}

// ---------------- prep: convert X to fp16 + routing ----------------
__global__ void prep_kernel(const float4* __restrict__ x,
                            const float* __restrict__ rw, const void* sel_raw) {
    if (blockIdx.x == NXB) {
        __shared__ int sc[N_EXP];
        __shared__ int scur[N_EXP];
        __shared__ int smode;
        int tid = threadIdx.x;
        if (tid < N_EXP) sc[tid] = 0;
        if (tid == 0) {
            const int* s32 = (const int*)sel_raw;
            int any = 0;
            #pragma unroll
            for (int i = 0; i < 8; i++) any |= s32[2 * i + 1];
            smode = any ? 0 : 1;  // 1 = int64
        }
        __syncthreads();
        int mode = smode;
        const long long* s64 = (const long long*)sel_raw;
        const int* s32 = (const int*)sel_raw;
        for (int i = tid; i < TK; i += blockDim.x) {
            int e = mode ? (int)s64[i] : s32[i];
            atomicAdd(&sc[e], 1);
        }
        __syncthreads();
        if (tid == 0) {
            int off = 0;
            for (int e = 0; e < N_EXP; e++) { g_offsets[e] = off; scur[e] = off; off += sc[e]; }
            g_offsets[N_EXP] = off;
        }
        __syncthreads();
        for (int i = tid; i < TK; i += blockDim.x) {
            int e = mode ? (int)s64[i] : s32[i];
            int p = atomicAdd(&scur[e], 1);
            g_tok[p] = i >> 1;
            g_pos[p] = i;
            g_wt[p] = rw[i];
        }
        return;
    }
    const int NX8 = T_TOK * D_DIM / 8;
    for (int i = blockIdx.x * blockDim.x + threadIdx.x; i < NX8;
         i += NXB * blockDim.x) {
        float4 v0 = x[2 * i];
        float4 v1 = x[2 * i + 1];
        uint4 o;
        o.x = pack_h2(v0.x, v0.y);
        o.y = pack_h2(v0.z, v0.w);
        o.z = pack_h2(v1.x, v1.y);
        o.w = pack_h2(v1.z, v1.w);
        ((uint4*)g_xh)[i] = o;
    }
}

// ---------------- gemm1 mainloop: fp16 A + f32 B staged->fp16 in smem -----
// Stage (20KB): [A fp16 8KB][B f32 8KB][B fp16 4KB].
// A fp16: row r, 16B chunk c(0..3) at r*64 + ((c^((r>>1)&3))<<4).
// B f32:  row r, 16B chunk c(0..7) at BF32_OFF + r*128 + ((c^(r&7))<<4).
// B fp16: row r, 16B chunk c(0..3) at BF16_OFF + r*64 + ((c^((r>>1)&3))<<4).
// Per kt: each warp converts its own (wn, wk) B slice: lane l owns row wn*32+l,
// reads f32 chunks 4wk..4wk+3, writes fp16 chunks 2wk..2wk+1, __syncwarp, ldsm.
__device__ __forceinline__ void mma_loop1(uint32_t smem0, const __half* a_row,
                                          const float* b_row, int KT,
                                          float cc[4][4][4]) {
    const int tid = threadIdx.x;
    const int lane = tid & 31;
    const int warp = tid >> 5;
    const int wk = warp >> 2;
    const int wm = (warp >> 1) & 1;
    const int wn = warp & 1;

    // A loader: row = tid>>1, 2 chunks
    const int ra = tid >> 1;
    uint32_t stA[2];
    #pragma unroll
    for (int i = 0; i < 2; i++) {
        const int c = (tid & 1) * 2 + i;
        stA[i] = (uint32_t)(ra * 64) + (uint32_t)(((c ^ ((ra >> 1) & 3)) << 4));
    }
    // B f32 loader: row = tid>>2, 2 chunks
    const int rbq = tid >> 2;
    uint32_t stB[2];
    int gB[2];
    #pragma unroll
    for (int i = 0; i < 2; i++) {
        const int c = (tid & 3) * 2 + i;
        stB[i] = (uint32_t)(BF32_OFF + rbq * 128) + (uint32_t)(((c ^ (rbq & 7)) << 4));
        gB[i] = c * 4;  // floats
    }

    // A ldsm addresses (stage-relative)
    const int arow_l = (lane & 7) + (lane & 8);
    const int achunk = 2 * wk + (lane >> 4);
    uint32_t a_off[4];
    #pragma unroll
    for (int mt = 0; mt < 4; mt++) {
        const int row = wm * 64 + mt * 16 + arow_l;
        a_off[mt] = (uint32_t)(row * 64) +
                    (uint32_t)(((achunk ^ ((arow_l >> 1) & 3)) << 4));
    }
    // B ldsm addresses (into fp16 region)
    const int brow_l = (lane & 7) + ((lane >> 4) << 3);
    const int bchunk = 2 * wk + ((lane >> 3) & 1);
    uint32_t b_off[2];
    #pragma unroll
    for (int n2 = 0; n2 < 2; n2++) {
        const int row = wn * 32 + n2 * 16 + brow_l;
        b_off[n2] = (uint32_t)(BF16_OFF + row * 64) +
                    (uint32_t)(((bchunk ^ ((row >> 1) & 3)) << 4));
    }
    // conversion addresses for this lane's row r = wn*32 + lane
    const int crow = wn * 32 + lane;
    const uint32_t cx = (uint32_t)(crow & 7);
    const uint32_t cxl = cx & 3;
    const uint32_t src_hi = (uint32_t)(BF32_OFF + crow * 128) +
                            ((((uint32_t)(4 * wk)) ^ (cx & 4)) << 4);
    const uint32_t cy = (uint32_t)((crow >> 1) & 3);
    const uint32_t cyl = cy & 1;
    const uint32_t dst_hi = (uint32_t)(BF16_OFF + crow * 64) +
                            ((((uint32_t)(2 * wk)) ^ (cy & 2)) << 4);

    auto load_stage = [&](int kt) {
        const uint32_t sb = smem0 + (uint32_t)((kt % NST1) * STG1);
        const __half* As = a_row + kt * 32;
        const float* Bs = b_row + kt * 32;
        #pragma unroll
        for (int i = 0; i < 2; i++)
            cpasync16(sb + stA[i], As + ((tid & 1) * 2 + i) * 8);
        #pragma unroll
        for (int i = 0; i < 2; i++)
            cpasync16(sb + stB[i], Bs + gB[i]);
        cp_commit();
    };

    #pragma unroll
    for (int s = 0; s < 4; s++) load_stage(s);

    for (int kt = 0; kt < KT; kt++) {
        const int rem = KT - 1 - kt;
        cp_waitg(rem < 3 ? rem : 3);
        __syncthreads();
        if (kt + 4 < KT) load_stage(kt + 4);

        const uint32_t base = smem0 + (uint32_t)((kt % NST1) * STG1);

        // convert this warp's B slice: f32 chunks 4wk+j -> fp16 chunks 2wk+j2
        #pragma unroll
        for (int j2 = 0; j2 < 2; j2++) {
            float4 f0, f1;
            {
                const uint32_t a0 = base + src_hi + ((((uint32_t)(2 * j2)) ^ cxl) << 4);
                const uint32_t a1 = base + src_hi + ((((uint32_t)(2 * j2 + 1)) ^ cxl) << 4);
                asm volatile("ld.shared.v4.f32 {%0,%1,%2,%3}, [%4];"
                             : "=f"(f0.x), "=f"(f0.y), "=f"(f0.z), "=f"(f0.w) : "r"(a0));
                asm volatile("ld.shared.v4.f32 {%0,%1,%2,%3}, [%4];"
                             : "=f"(f1.x), "=f"(f1.y), "=f"(f1.z), "=f"(f1.w) : "r"(a1));
            }
            uint32_t h0 = pack_h2(f0.x, f0.y);
            uint32_t h1 = pack_h2(f0.z, f0.w);
            uint32_t h2 = pack_h2(f1.x, f1.y);
            uint32_t h3 = pack_h2(f1.z, f1.w);
            const uint32_t d = base + dst_hi + ((((uint32_t)j2) ^ cyl) << 4);
            asm volatile("st.shared.v4.b32 [%0], {%1,%2,%3,%4};"
                         ::"r"(d), "r"(h0), "r"(h1), "r"(h2), "r"(h3) : "memory");
        }
        __syncwarp();

        uint32_t a[4][4], b[2][4];
        #pragma unroll
        for (int mt = 0; mt < 4; mt++)
            ldsm4(a[mt], base + a_off[mt]);
        #pragma unroll
        for (int n2 = 0; n2 < 2; n2++)
            ldsm4(b[n2], base + b_off[n2]);
        #pragma unroll
        for (int mt = 0; mt < 4; mt++)
            #pragma unroll
            for (int nt = 0; nt < 4; nt++)
                mma_f16(cc[mt][nt], a[mt], b[nt >> 1][(nt & 1) * 2],
                        b[nt >> 1][(nt & 1) * 2 + 1]);
    }

    // k-split reduction
    __syncthreads();
    const uint32_t redb = smem0 + (uint32_t)((warp & 3) * 8192);
    if (wk == 1) {
        #pragma unroll
        for (int mt = 0; mt < 4; mt++)
            #pragma unroll
            for (int nt = 0; nt < 4; nt++) {
                uint32_t addr = redb + (uint32_t)(((mt * 4 + nt) * 32 + lane) * 16);
                asm volatile("st.shared.v4.b32 [%0], {%1,%2,%3,%4};" ::"r"(addr),
                             "r"(__float_as_uint(cc[mt][nt][0])),
                             "r"(__float_as_uint(cc[mt][nt][1])),
                             "r"(__float_as_uint(cc[mt][nt][2])),
                             "r"(__float_as_uint(cc[mt][nt][3])) : "memory");
            }
    }
    __syncthreads();
    if (wk == 0) {
        #pragma unroll
        for (int mt = 0; mt < 4; mt++)
            #pragma unroll
            for (int nt = 0; nt < 4; nt++) {
                uint32_t addr = redb + (uint32_t)(((mt * 4 + nt) * 32 + lane) * 16);
                uint32_t r0, r1, r2, r3;
                asm volatile("ld.shared.v4.b32 {%0,%1,%2,%3}, [%4];"
                             : "=r"(r0), "=r"(r1), "=r"(r2), "=r"(r3) : "r"(addr));
                cc[mt][nt][0] += __uint_as_float(r0);
                cc[mt][nt][1] += __uint_as_float(r1);
                cc[mt][nt][2] += __uint_as_float(r2);
                cc[mt][nt][3] += __uint_as_float(r3);
            }
    }
    __syncthreads();
}

// ---------------- gemm2 mainloop: R15's fp16 path (6 stages) ----------------
__device__ __forceinline__ void mma_loop2(uint32_t smem0, const __half* a_row,
                                          const __half* b_row, int KT,
                                          float cc[4][4][4]) {
    const int tid = threadIdx.x;
    const int lane = tid & 31;
    const int warp = tid >> 5;
    const int wk = warp >> 2;
    const int wm = (warp >> 1) & 1;
    const int wn = warp & 1;

    const int ra = tid >> 1;
    const int rb = tid >> 2;
    uint32_t stA[2], stB;
    #pragma unroll
    for (int i = 0; i < 2; i++) {
        const int c = (tid & 1) * 2 + i;
        stA[i] = (uint32_t)(ra * 64) + (uint32_t)(((c ^ ((ra >> 1) & 3)) << 4));
    }
    {
        const int c = tid & 3;
        stB = (uint32_t)(A_ST + rb * 64) + (uint32_t)(((c ^ ((rb >> 1) & 3)) << 4));
    }

    const int arow_l = (lane & 7) + (lane & 8);
    const int brow_l = (lane & 7) + ((lane >> 4) << 3);
    const int achunk = 2 * wk + (lane >> 4);
    const int bchunk = 2 * wk + ((lane >> 3) & 1);
    uint32_t a_off[4], b_off[2];
    #pragma unroll
    for (int mt = 0; mt < 4; mt++) {
        const int row = wm * 64 + mt * 16 + arow_l;
        a_off[mt] = (uint32_t)(row * 64) +
                    (uint32_t)(((achunk ^ ((arow_l >> 1) & 3)) << 4));
    }
    #pragma unroll
    for (int n2 = 0; n2 < 2; n2++) {
        const int row = wn * 32 + n2 * 16 + brow_l;
        b_off[n2] = (uint32_t)(A_ST + row * 64) +
                    (uint32_t)(((bchunk ^ ((row >> 1) & 3)) << 4));
    }

    auto load_stage = [&](int kt) {
        const uint32_t sb = smem0 + (uint32_t)((kt % NST2) * STG2);
        const __half* As = a_row + kt * 32;
        const __half* Bs = b_row + kt * 32;
        #pragma unroll
        for (int i = 0; i < 2; i++)
            cpasync16(sb + stA[i], As + ((tid & 1) * 2 + i) * 8);
        cpasync16(sb + stB, Bs + (tid & 3) * 8);
        cp_commit();
    };

    #pragma unroll
    for (int s = 0; s < 5; s++) load_stage(s);

    for (int kt = 0; kt < KT; kt++) {
        const int rem = KT - 1 - kt;
        cp_waitg(rem < 4 ? rem : 4);
        __syncthreads();
        if (kt + 5 < KT) load_stage(kt + 5);

        const uint32_t base = smem0 + (uint32_t)((kt % NST2) * STG2);
        uint32_t a[4][4], b[2][4];
        #pragma unroll
        for (int mt = 0; mt < 4; mt++)
            ldsm4(a[mt], base + a_off[mt]);
        #pragma unroll
        for (int n2 = 0; n2 < 2; n2++)
            ldsm4(b[n2], base + b_off[n2]);
        #pragma unroll
        for (int mt = 0; mt < 4; mt++)
            #pragma unroll
            for (int nt = 0; nt < 4; nt++)
                mma_f16(cc[mt][nt], a[mt], b[nt >> 1][(nt & 1) * 2],
                        b[nt >> 1][(nt & 1) * 2 + 1]);
    }

    __syncthreads();
    const uint32_t redb = smem0 + (uint32_t)((warp & 3) * 8192);
    if (wk == 1) {
        #pragma unroll
        for (int mt = 0; mt < 4; mt++)
            #pragma unroll
            for (int nt = 0; nt < 4; nt++) {
                uint32_t addr = redb + (uint32_t)(((mt * 4 + nt) * 32 + lane) * 16);
                asm volatile("st.shared.v4.b32 [%0], {%1,%2,%3,%4};" ::"r"(addr),
                             "r"(__float_as_uint(cc[mt][nt][0])),
                             "r"(__float_as_uint(cc[mt][nt][1])),
                             "r"(__float_as_uint(cc[mt][nt][2])),
                             "r"(__float_as_uint(cc[mt][nt][3])) : "memory");
            }
    }
    __syncthreads();
    if (wk == 0) {
        #pragma unroll
        for (int mt = 0; mt < 4; mt++)
            #pragma unroll
            for (int nt = 0; nt < 4; nt++) {
                uint32_t addr = redb + (uint32_t)(((mt * 4 + nt) * 32 + lane) * 16);
                uint32_t r0, r1, r2, r3;
                asm volatile("ld.shared.v4.b32 {%0,%1,%2,%3}, [%4];"
                             : "=r"(r0), "=r"(r1), "=r"(r2), "=r"(r3) : "r"(addr));
                cc[mt][nt][0] += __uint_as_float(r0);
                cc[mt][nt][1] += __uint_as_float(r1);
                cc[mt][nt][2] += __uint_as_float(r2);
                cc[mt][nt][3] += __uint_as_float(r3);
            }
    }
    __syncthreads();
}

// ---------------- GEMM1: X @ Wgu^T (+SwiGLU) -> g_h; riders convert Wd ----
__global__ void __launch_bounds__(256, 2)
gemm1_k(const float* __restrict__ Wgu, const float4* __restrict__ wd_src) {
    if (blockIdx.y >= G1Y) {
        const int cb = (blockIdx.z * WDCVT_Y + (blockIdx.y - G1Y)) * GRIDX + blockIdx.x;
        const int ND8 = N_EXP * D_DIM * F_DIM / 8;
        uint4* dst = (uint4*)g_wdh;
        const int nblk = GRIDX * WDCVT_Y * N_EXP;
        for (int i = cb * 256 + threadIdx.x; i < ND8; i += nblk * 256) {
            float4 v0 = wd_src[2 * i];
            float4 v1 = wd_src[2 * i + 1];
            uint4 o;
            o.x = pack_h2(v0.x, v0.y);
            o.y = pack_h2(v0.z, v0.w);
            o.z = pack_h2(v1.x, v1.y);
            o.w = pack_h2(v1.z, v1.w);
            dst[i] = o;
        }
        return;
    }

    const int e = blockIdx.z;
    const int base = g_offsets[e];
    const int n_e = g_offsets[e + 1] - base;
    const int col0 = blockIdx.y * 32;

    extern __shared__ __align__(128) char smraw[];
    const uint32_t smem0 = cvta_s(smraw);
    const int tid = threadIdx.x;
    const int lane = tid & 31, warp = tid >> 5;
    const int wk = warp >> 2;
    const int wm = (warp >> 1) & 1, wn = warp & 1;

    const int nrow = tid >> 2;
    const int wrow = col0 + (nrow >> 1) + ((nrow & 1) ? F_DIM : 0);
    const float* b_row = Wgu + ((size_t)e * F2_DIM + wrow) * D_DIM;

    for (int rb2 = blockIdx.x; rb2 * 128 < n_e; rb2 += GRIDX) {
        const int row0 = rb2 * 128;
        int ge = base + row0 + (tid >> 1);
        if (ge > TK - 1) ge = TK - 1;
        const __half* a_row = g_xh + (size_t)g_tok[ge] * D_DIM;

        float cc[4][4][4];
        #pragma unroll
        for (int a = 0; a < 4; a++)
            #pragma unroll
            for (int b = 0; b < 4; b++)
                #pragma unroll
                for (int c = 0; c < 4; c++) cc[a][b][c] = 0.f;

        mma_loop1(smem0, a_row, b_row, D_DIM / 32, cc);

        if (wk == 0) {
            const int rbase = wm * 64 + (lane >> 2);
            const int jbase = col0 + wn * 16 + (lane & 3);
            #pragma unroll
            for (int mt = 0; mt < 4; mt++) {
                const int r0 = rbase + mt * 16;
                #pragma unroll
                for (int nt = 0; nt < 4; nt++) {
                    const int j = jbase + (nt >> 1) * 8 + (nt & 1) * 4;
                    if (row0 + r0 < n_e) {
                        float g = cc[mt][nt][0], u = cc[mt][nt][1];
                        float h = g * u / (1.f + __expf(-g));
                        g_h[(size_t)(base + row0 + r0) * F_DIM + j] = __float2half_rn(h);
                    }
                    if (row0 + r0 + 8 < n_e) {
                        float g = cc[mt][nt][2], u = cc[mt][nt][3];
                        float h = g * u / (1.f + __expf(-g));
                        g_h[(size_t)(base + row0 + r0 + 8) * F_DIM + j] = __float2half_rn(h);
                    }
                }
            }
        }
    }
}

// ---------------- GEMM2: g_h @ Wd^T (fp16), scale, per-slot store ---------
__global__ void __launch_bounds__(256, 2)
gemm2_k() {
    const int e = blockIdx.z;
    const int base = g_offsets[e];
    const int n_e = g_offsets[e + 1] - base;
    const int col0 = blockIdx.y * 64;

    extern __shared__ __align__(128) char smraw[];
    const uint32_t smem0 = cvta_s(smraw);
    const int tid = threadIdx.x;
    const int lane = tid & 31, warp = tid >> 5;
    const int wk = warp >> 2;
    const int wm = (warp >> 1) & 1, wn = warp & 1;

    const __half* b_row = g_wdh + ((size_t)e * D_DIM + col0 + (tid >> 2)) * F_DIM;

    for (int rb2 = blockIdx.x; rb2 * 128 < n_e; rb2 += GRIDX) {
        const int row0 = rb2 * 128;
        int ge = base + row0 + (tid >> 1);
        if (ge > TK - 1) ge = TK - 1;
        const __half* a_row = g_h + (size_t)ge * F_DIM;

        float cc[4][4][4];
        #pragma unroll
        for (int a = 0; a < 4; a++)
            #pragma unroll
            for (int b = 0; b < 4; b++)
                #pragma unroll
                for (int c = 0; c < 4; c++) cc[a][b][c] = 0.f;

        mma_loop2(smem0, a_row, b_row, F_DIM / 32, cc);

        if (wk == 0) {
            const int rbase = wm * 64 + (lane >> 2);
            const int colb = col0 + wn * 32 + 2 * (lane & 3);
            #pragma unroll
            for (int mt = 0; mt < 4; mt++) {
                const int r0 = rbase + mt * 16;
                #pragma unroll
                for (int half = 0; half < 2; half++) {
                    const int r = r0 + half * 8;
                    if (row0 + r < n_e) {
                        const int gi = base + row0 + r;
                        const int pos = g_pos[gi];
                        const float wt = g_wt[gi];
                        float* orow = g_o + (size_t)pos * D_DIM;
                        #pragma unroll
                        for (int nt = 0; nt < 4; nt++) {
                            const int col = colb + (nt >> 1) * 16 + (nt & 1) * 8;
                            float2 v;
                            v.x = cc[mt][nt][half * 2 + 0] * wt;
                            v.y = cc[mt][nt][half * 2 + 1] * wt;
                            *(float2*)(orow + col) = v;
                        }
                    }
                }
            }
        }
    }
}

// ---------------- combine the 2 slots per token ----------------
__global__ void combine_kernel(float4* __restrict__ out) {
    const int RD = D_DIM / 4;
    int i = blockIdx.x * blockDim.x + threadIdx.x;
    if (i < T_TOK * RD) {
        int t = i / RD, r = i % RD;
        const float4* go = (const float4*)g_o;
        float4 a = go[(size_t)(2 * t) * RD + r];
        float4 b = go[(size_t)(2 * t + 1) * RD + r];
        out[i] = make_float4(a.x + b.x, a.y + b.y, a.z + b.z, a.w + b.w);
    }
}

// ---------------- launch ----------------
extern "C" void kernel_launch(void* const* d_in, const int* in_sizes, int n_in,
                              void* d_out, int out_size) {
    const float* X   = (const float*)d_in[0];
    const float* rw  = (const float*)d_in[1];
    const float* Wgu = (const float*)d_in[2];
    const float* Wd  = (const float*)d_in[3];
    const void*  sel = d_in[4];
    float* out = (float*)d_out;

    cudaFuncSetAttribute(gemm1_k, cudaFuncAttributeMaxDynamicSharedMemorySize, SMEM1);
    cudaFuncSetAttribute(gemm2_k, cudaFuncAttributeMaxDynamicSharedMemorySize, SMEM2);

    prep_kernel<<<NXB + 1, 256>>>((const float4*)X, rw, sel);
    gemm1_k<<<dim3(GRIDX, G1Y + WDCVT_Y, N_EXP), 256, SMEM1>>>(Wgu, (const float4*)Wd);
    gemm2_k<<<dim3(GRIDX, D_DIM / 64, N_EXP), 256, SMEM2>>>();
    combine_kernel<<<(T_TOK * D_DIM / 4 + 255) / 256, 256>>>((float4*)out);
}